// round 6
// baseline (speedup 1.0000x reference)
#include <cuda_runtime.h>
#include <math.h>

// ---- problem constants ----
#define D_   2048
#define H_   16
#define KVH_ 4
#define HD_  128
#define B_   2
#define T_   2048
#define BT_  (B_*T_)          // 4096
#define QCOLS_ (H_*HD_)       // 2048
#define KCOLS_ (KVH_*HD_)     // 512
#define CAP_ 50.0f
#define SCALE_ 0.08838834764831845f  // 128^-0.5

// ---- scratch (static device arrays; no allocations allowed) ----
static __device__ float g_q[BT_*QCOLS_];
static __device__ float g_k[BT_*KCOLS_];
static __device__ float g_v[BT_*KCOLS_];
static __device__ float g_o[BT_*QCOLS_];

// ============================================================================
// tf32 mma helpers
// ============================================================================
__device__ __forceinline__ unsigned f2tf32(float x) {
    unsigned u;
    asm("cvt.rna.tf32.f32 %0, %1;" : "=r"(u) : "f"(x));
    return u;
}

__device__ __forceinline__ void mma_tf32(float* c, const unsigned* a, const unsigned* b) {
    asm volatile(
        "mma.sync.aligned.m16n8k8.row.col.f32.tf32.tf32.f32 "
        "{%0,%1,%2,%3}, {%4,%5,%6,%7}, {%8,%9}, {%0,%1,%2,%3};"
        : "+f"(c[0]), "+f"(c[1]), "+f"(c[2]), "+f"(c[3])
        : "r"(a[0]), "r"(a[1]), "r"(a[2]), "r"(a[3]), "r"(b[0]), "r"(b[1]));
}

__device__ __forceinline__ float tanh_fast(float x) {
    float r;
    asm("tanh.approx.f32 %0, %1;" : "=f"(r) : "f"(x));
    return r;
}

// ============================================================================
// tf32 GEMM v2: C[M,N] = A[M,K]*B[N,K]^T. 128x128x32 tiles, 256 thr, 8 warps
// (4x2), warp 32x64. tf32 pre-converted at STS into pair-permuted smem
// (perm(k) = (k>>3)*8 + (k&3)*2 + ((k>>2)&1), row stride 40): every fragment
// load is a conflict-free LDS.64. Double-buffered stages, 1 sync/iter.
// ============================================================================
#define BK_ 32
#define GLDP 40
#define GSTAGE (128*GLDP)
#define GEMM_SMEM (4*GSTAGE*(int)sizeof(unsigned))   // 2 stages x (A+B) = 80KB

__global__ __launch_bounds__(256, 2) void gemm_tf32(
    const float* __restrict__ A, const float* __restrict__ Bw,
    float* __restrict__ C, int M, int N, int K)
{
    extern __shared__ unsigned gsm[];
    const int tid  = threadIdx.x;
    const int lane = tid & 31;
    const int warp = tid >> 5;
    const int gid  = lane >> 2, m4 = lane & 3;
    const int wm = (warp & 3) * 32;
    const int wn = (warp >> 2) * 64;
    const int rowBase = blockIdx.y * 128;
    const int colBase = blockIdx.x * 128;

    const int lr = tid >> 3;                 // 0..31 (row sub-index)
    const int s8 = tid & 7;                  // k-chunk: loads k = 4*s8..4*s8+3
    const int stsoff = 8 * (s8 >> 1) + (s8 & 1);

    float acc[2][8][4];
#pragma unroll
    for (int mi = 0; mi < 2; mi++)
#pragma unroll
        for (int ni = 0; ni < 8; ni++)
#pragma unroll
            for (int q = 0; q < 4; q++) acc[mi][ni][q] = 0.f;

    const int nt = K / BK_;
    float4 av[4], bv[4];

    // ---- LDG + STS stage 0 ----
#pragma unroll
    for (int it = 0; it < 4; it++) {
        int r = it * 32 + lr;
        av[it] = *(const float4*)(A  + (size_t)(rowBase + r) * K + 4 * s8);
        bv[it] = *(const float4*)(Bw + (size_t)(colBase + r) * K + 4 * s8);
    }
#pragma unroll
    for (int it = 0; it < 4; it++) {
        int r = it * 32 + lr;
        unsigned* ua = gsm + r * GLDP + stsoff;
        ua[0] = f2tf32(av[it].x); ua[2] = f2tf32(av[it].y);
        ua[4] = f2tf32(av[it].z); ua[6] = f2tf32(av[it].w);
        unsigned* ub = gsm + GSTAGE + r * GLDP + stsoff;
        ub[0] = f2tf32(bv[it].x); ub[2] = f2tf32(bv[it].y);
        ub[4] = f2tf32(bv[it].z); ub[6] = f2tf32(bv[it].w);
    }

    int cur = 0;
    for (int t = 0; t < nt; t++) {
        __syncthreads();

        if (t + 1 < nt) {
            int k0 = (t + 1) * BK_;
#pragma unroll
            for (int it = 0; it < 4; it++) {
                int r = it * 32 + lr;
                av[it] = *(const float4*)(A  + (size_t)(rowBase + r) * K + k0 + 4 * s8);
                bv[it] = *(const float4*)(Bw + (size_t)(colBase + r) * K + k0 + 4 * s8);
            }
        }

        const unsigned* as = gsm + (cur ? 2 * GSTAGE : 0);
        const unsigned* bs = as + GSTAGE;
#pragma unroll
        for (int kc = 0; kc < 4; kc++) {
            unsigned af[2][4];
#pragma unroll
            for (int mi = 0; mi < 2; mi++) {
                int r = wm + 16 * mi + gid;
                uint2 lo = *(const uint2*)(as + r       * GLDP + 8 * kc + 2 * m4);
                uint2 hi = *(const uint2*)(as + (r + 8) * GLDP + 8 * kc + 2 * m4);
                af[mi][0] = lo.x; af[mi][2] = lo.y;
                af[mi][1] = hi.x; af[mi][3] = hi.y;
            }
#pragma unroll
            for (int ni = 0; ni < 8; ni++) {
                uint2 bb = *(const uint2*)(bs + (wn + 8 * ni + gid) * GLDP + 8 * kc + 2 * m4);
                unsigned bf[2] = { bb.x, bb.y };
                mma_tf32(acc[0][ni], af[0], bf);
                mma_tf32(acc[1][ni], af[1], bf);
            }
        }

        if (t + 1 < nt) {
            unsigned* asn = gsm + (cur ? 0 : 2 * GSTAGE);
            unsigned* bsn = asn + GSTAGE;
#pragma unroll
            for (int it = 0; it < 4; it++) {
                int r = it * 32 + lr;
                unsigned* ua = asn + r * GLDP + stsoff;
                ua[0] = f2tf32(av[it].x); ua[2] = f2tf32(av[it].y);
                ua[4] = f2tf32(av[it].z); ua[6] = f2tf32(av[it].w);
                unsigned* ub = bsn + r * GLDP + stsoff;
                ub[0] = f2tf32(bv[it].x); ub[2] = f2tf32(bv[it].y);
                ub[4] = f2tf32(bv[it].z); ub[6] = f2tf32(bv[it].w);
            }
        }
        cur ^= 1;
    }

    // ---- epilogue ----
#pragma unroll
    for (int mi = 0; mi < 2; mi++) {
        int r0 = rowBase + wm + 16 * mi + gid;
#pragma unroll
        for (int ni = 0; ni < 8; ni++) {
            int c0 = colBase + wn + ni * 8 + m4 * 2;
            *(float2*)&C[(size_t)r0       * N + c0] = make_float2(acc[mi][ni][0], acc[mi][ni][1]);
            *(float2*)&C[(size_t)(r0 + 8) * N + c0] = make_float2(acc[mi][ni][2], acc[mi][ni][3]);
        }
    }
}

// ============================================================================
// RMSNorm: one warp per 128-element row, in place.
// ============================================================================
__global__ __launch_bounds__(256) void rmsnorm_k(
    float* __restrict__ data, const float* __restrict__ gamma,
    int nrows, float scale)
{
    int row  = blockIdx.x * 8 + (threadIdx.x >> 5);
    int lane = threadIdx.x & 31;
    if (row >= nrows) return;
    float4 v = ((float4*)data)[(size_t)row * 32 + lane];
    float ss = v.x*v.x + v.y*v.y + v.z*v.z + v.w*v.w;
#pragma unroll
    for (int off = 16; off > 0; off >>= 1)
        ss += __shfl_xor_sync(0xffffffffu, ss, off);
    float r = rsqrtf(ss * (1.0f/128.0f) + 1e-6f) * scale;
    float4 g = ((const float4*)gamma)[lane];
    v.x *= r * g.x; v.y *= r * g.y; v.z *= r * g.z; v.w *= r * g.w;
    ((float4*)data)[(size_t)row * 32 + lane] = v;
}

// ============================================================================
// Tensor-core flash attention v2 (causal, tanh softcap).
// CTA: 128 thr (4 warps in 2x2: wm = q-half, wn = key-half). Tile 64q x 64k.
// Warp tile M=32 (2 m-frags, B-frag reuse) x N=32. Each wn-half runs an
// independent online softmax; halves merged once at the epilogue via smem.
// Layouts (tf32, pre-converted at store):
//   Qs/Ks [64][136] pair-permuted -> all QK frag loads are LDS.64 bank-free.
//   Vt: (key,d) -> (d>>2)*260 + 8*(key>>1) + 2*(d&3) + (key&1): PV B-frag
//       (key pair) is one LDS.64, bank-free.
// ============================================================================
#define AT_LDK 136
#define AT_VROW 260
#define ATTN_SMEM ((2*64*AT_LDK + 32*AT_VROW) * (int)sizeof(unsigned))  // ~100.5KB

__global__ __launch_bounds__(128) void attn_mma(
    const float* __restrict__ Q, const float* __restrict__ Kk,
    const float* __restrict__ Vv, float* __restrict__ O)
{
    extern __shared__ unsigned smu[];
    unsigned* Qs = smu;
    unsigned* Ks = Qs + 64 * AT_LDK;
    unsigned* Vt = Ks + 64 * AT_LDK;

    const int tid  = threadIdx.x;
    const int lane = tid & 31;
    const int warp = tid >> 5;
    const int gid  = lane >> 2, m4 = lane & 3;
    const int wm = warp & 1;          // q-half
    const int wn = warp >> 1;         // key-half

    const int bh = blockIdx.y;
    const int b = bh >> 4, h = bh & 15, kvh = h >> 2;
    const int qt = gridDim.x - 1 - blockIdx.x;
    const int qBase = qt * 64;

    const float* qp = Q  + (size_t)b*T_*QCOLS_ + (size_t)h*HD_;
    const float* kp = Kk + (size_t)b*T_*KCOLS_ + (size_t)kvh*HD_;
    const float* vp = Vv + (size_t)b*T_*KCOLS_ + (size_t)kvh*HD_;

    // ---- load Q (64x128) -> Qs, tf32, pair-permuted ----
#pragma unroll
    for (int it = 0; it < 16; it++) {
        int i = it * 128 + tid;
        int r = i >> 5;
        int ln = i & 31;
        float4 v = *(const float4*)(qp + (size_t)(qBase + r) * QCOLS_ + 4 * ln);
        unsigned* d = Qs + r * AT_LDK + 8 * (ln >> 1) + (ln & 1);
        d[0] = f2tf32(v.x); d[2] = f2tf32(v.y);
        d[4] = f2tf32(v.z); d[6] = f2tf32(v.w);
    }

    float m[2][2], l[2][2], o[2][16][4];
#pragma unroll
    for (int mf = 0; mf < 2; mf++) {
        m[mf][0] = -INFINITY; m[mf][1] = -INFINITY;
        l[mf][0] = 0.f; l[mf][1] = 0.f;
#pragma unroll
        for (int nf = 0; nf < 16; nf++)
#pragma unroll
            for (int q = 0; q < 4; q++) o[mf][nf][q] = 0.f;
    }

    for (int jt = 0; jt <= qt; jt++) {
        const int kBase = jt * 64;

        // ---- load K -> Ks (permuted), V -> Vt ----
#pragma unroll
        for (int it = 0; it < 16; it++) {
            int i = it * 128 + tid;
            int r = i >> 5;
            int ln = i & 31;
            float4 kv = *(const float4*)(kp + (size_t)(kBase + r) * KCOLS_ + 4 * ln);
            unsigned* kd = Ks + r * AT_LDK + 8 * (ln >> 1) + (ln & 1);
            kd[0] = f2tf32(kv.x); kd[2] = f2tf32(kv.y);
            kd[4] = f2tf32(kv.z); kd[6] = f2tf32(kv.w);
            float4 vv = *(const float4*)(vp + (size_t)(kBase + r) * KCOLS_ + 4 * ln);
            unsigned* vd = Vt + ln * AT_VROW + 8 * (r >> 1) + (r & 1);
            vd[0] = f2tf32(vv.x); vd[2] = f2tf32(vv.y);
            vd[4] = f2tf32(vv.z); vd[6] = f2tf32(vv.w);
        }
        __syncthreads();

        // ---- S = Q.K^T ----
        float s[2][4][4];
#pragma unroll
        for (int mf = 0; mf < 2; mf++)
#pragma unroll
            for (int nf = 0; nf < 4; nf++)
#pragma unroll
                for (int q = 0; q < 4; q++) s[mf][nf][q] = 0.f;

#pragma unroll
        for (int kc = 0; kc < 16; kc++) {
            unsigned af[2][4];
#pragma unroll
            for (int mf = 0; mf < 2; mf++) {
                int r = 32 * wm + 16 * mf + gid;
                uint2 lo = *(const uint2*)(Qs + r       * AT_LDK + 8 * kc + 2 * m4);
                uint2 hi = *(const uint2*)(Qs + (r + 8) * AT_LDK + 8 * kc + 2 * m4);
                af[mf][0] = lo.x; af[mf][2] = lo.y;
                af[mf][1] = hi.x; af[mf][3] = hi.y;
            }
#pragma unroll
            for (int nf = 0; nf < 4; nf++) {
                uint2 bb = *(const uint2*)(Ks + (32 * wn + 8 * nf + gid) * AT_LDK + 8 * kc + 2 * m4);
                unsigned bf[2] = { bb.x, bb.y };
                mma_tf32(s[0][nf], af[0], bf);
                mma_tf32(s[1][nf], af[1], bf);
            }
        }

        // ---- softcap + causal mask ----
#pragma unroll
        for (int mf = 0; mf < 2; mf++) {
            int rb = qBase + 32 * wm + 16 * mf + gid;
#pragma unroll
            for (int nf = 0; nf < 4; nf++) {
#pragma unroll
                for (int q = 0; q < 4; q++) {
                    int col = kBase + 32 * wn + 8 * nf + 2 * m4 + (q & 1);
                    int row = rb + ((q & 2) << 2);
                    float val = CAP_ * tanh_fast(s[mf][nf][q] * (1.0f / CAP_));
                    s[mf][nf][q] = (col > row) ? -INFINITY : val;
                }
            }
        }

        // ---- online softmax per m-frag (guarded for all-masked strips) ----
#pragma unroll
        for (int mf = 0; mf < 2; mf++) {
            float rmax0 = -INFINITY, rmax1 = -INFINITY;
#pragma unroll
            for (int nf = 0; nf < 4; nf++) {
                rmax0 = fmaxf(rmax0, fmaxf(s[mf][nf][0], s[mf][nf][1]));
                rmax1 = fmaxf(rmax1, fmaxf(s[mf][nf][2], s[mf][nf][3]));
            }
#pragma unroll
            for (int off = 1; off <= 2; off <<= 1) {
                rmax0 = fmaxf(rmax0, __shfl_xor_sync(0xffffffffu, rmax0, off));
                rmax1 = fmaxf(rmax1, __shfl_xor_sync(0xffffffffu, rmax1, off));
            }
            float mn0 = fmaxf(m[mf][0], rmax0);
            float mn1 = fmaxf(m[mf][1], rmax1);
            float mn0e = (mn0 == -INFINITY) ? 0.f : mn0;
            float mn1e = (mn1 == -INFINITY) ? 0.f : mn1;
            float al0 = __expf(m[mf][0] - mn0e);
            float al1 = __expf(m[mf][1] - mn1e);
            m[mf][0] = mn0; m[mf][1] = mn1;

            float rs0 = 0.f, rs1 = 0.f;
#pragma unroll
            for (int nf = 0; nf < 4; nf++) {
                float p0 = __expf(s[mf][nf][0] - mn0e);
                float p1 = __expf(s[mf][nf][1] - mn0e);
                float p2 = __expf(s[mf][nf][2] - mn1e);
                float p3 = __expf(s[mf][nf][3] - mn1e);
                rs0 += p0 + p1; rs1 += p2 + p3;
                s[mf][nf][0] = p0; s[mf][nf][1] = p1;
                s[mf][nf][2] = p2; s[mf][nf][3] = p3;
            }
#pragma unroll
            for (int off = 1; off <= 2; off <<= 1) {
                rs0 += __shfl_xor_sync(0xffffffffu, rs0, off);
                rs1 += __shfl_xor_sync(0xffffffffu, rs1, off);
            }
            l[mf][0] = l[mf][0] * al0 + rs0;
            l[mf][1] = l[mf][1] * al1 + rs1;
#pragma unroll
            for (int nf = 0; nf < 16; nf++) {
                o[mf][nf][0] *= al0; o[mf][nf][1] *= al0;
                o[mf][nf][2] *= al1; o[mf][nf][3] *= al1;
            }
        }

        // ---- O += P.V (kappa-permuted, B-frag shared across m-frags) ----
#pragma unroll
        for (int kc = 0; kc < 4; kc++) {
            unsigned pa[2][4];
#pragma unroll
            for (int mf = 0; mf < 2; mf++) {
                pa[mf][0] = f2tf32(s[mf][kc][0]);
                pa[mf][1] = f2tf32(s[mf][kc][2]);
                pa[mf][2] = f2tf32(s[mf][kc][1]);
                pa[mf][3] = f2tf32(s[mf][kc][3]);
            }
            const int base = (gid >> 2) * AT_VROW + 32 * (4 * wn + kc) + 8 * m4 + 2 * (gid & 3);
#pragma unroll
            for (int nf = 0; nf < 16; nf++) {
                uint2 bb = *(const uint2*)(Vt + 2 * nf * AT_VROW + base);
                unsigned bv[2] = { bb.x, bb.y };
                mma_tf32(o[0][nf], pa[0], bv);
                mma_tf32(o[1][nf], pa[1], bv);
            }
        }
        __syncthreads();
    }

    // ---- epilogue: merge the two key-halves, divide by l, store ----
    float* fb = (float*)smu;            // O1 buffer [64][132]
    float* mb = fb + 64 * 132;          // m1 per row
    float* lb = mb + 64;                // l1 per row

    if (wn == 1) {
#pragma unroll
        for (int mf = 0; mf < 2; mf++) {
            int rl = 32 * wm + 16 * mf + gid;
#pragma unroll
            for (int nf = 0; nf < 16; nf++) {
                int c = 8 * nf + 2 * m4;
                *(float2*)(fb + rl * 132 + c)       = make_float2(o[mf][nf][0], o[mf][nf][1]);
                *(float2*)(fb + (rl + 8) * 132 + c) = make_float2(o[mf][nf][2], o[mf][nf][3]);
            }
            if (m4 == 0) {
                mb[rl] = m[mf][0];     lb[rl] = l[mf][0];
                mb[rl + 8] = m[mf][1]; lb[rl + 8] = l[mf][1];
            }
        }
    }
    __syncthreads();

    if (wn == 0) {
#pragma unroll
        for (int mf = 0; mf < 2; mf++) {
            int rl = 32 * wm + 16 * mf + gid;
            float m1a = mb[rl],     l1a = lb[rl];
            float m1b = mb[rl + 8], l1b = lb[rl + 8];
            float ms0 = fmaxf(m[mf][0], m1a);
            float ms1 = fmaxf(m[mf][1], m1b);
            float f00 = __expf(m[mf][0] - ms0), f01 = __expf(m1a - ms0);
            float f10 = __expf(m[mf][1] - ms1), f11 = __expf(m1b - ms1);
            float inv0 = 1.0f / (f00 * l[mf][0] + f01 * l1a);
            float inv1 = 1.0f / (f10 * l[mf][1] + f11 * l1b);

            float* op0 = O + ((size_t)b*T_ + qBase + rl)     * QCOLS_ + (size_t)h*HD_;
            float* op1 = O + ((size_t)b*T_ + qBase + rl + 8) * QCOLS_ + (size_t)h*HD_;
#pragma unroll
            for (int nf = 0; nf < 16; nf++) {
                int c = 8 * nf + 2 * m4;
                float2 p0 = *(float2*)(fb + rl * 132 + c);
                float2 p1 = *(float2*)(fb + (rl + 8) * 132 + c);
                *(float2*)(op0 + c) = make_float2((f00 * o[mf][nf][0] + f01 * p0.x) * inv0,
                                                  (f00 * o[mf][nf][1] + f01 * p0.y) * inv0);
                *(float2*)(op1 + c) = make_float2((f10 * o[mf][nf][2] + f11 * p1.x) * inv1,
                                                  (f10 * o[mf][nf][3] + f11 * p1.y) * inv1);
            }
        }
    }
}

// ============================================================================
// launch
// ============================================================================
extern "C" void kernel_launch(void* const* d_in, const int* in_sizes, int n_in,
                              void* d_out, int out_size)
{
    const float* x  = (const float*)d_in[0];
    const float* wq = (const float*)d_in[1];
    const float* wk = (const float*)d_in[2];
    const float* wv = (const float*)d_in[3];
    const float* wo = (const float*)d_in[4];
    const float* qg = (const float*)d_in[5];
    const float* kg = (const float*)d_in[6];
    float* out = (float*)d_out;

    float *q, *k, *v, *o;
    cudaGetSymbolAddress((void**)&q, g_q);
    cudaGetSymbolAddress((void**)&k, g_k);
    cudaGetSymbolAddress((void**)&v, g_v);
    cudaGetSymbolAddress((void**)&o, g_o);

    static bool attr_set = false;
    if (!attr_set) {
        cudaFuncSetAttribute(gemm_tf32, cudaFuncAttributeMaxDynamicSharedMemorySize, GEMM_SMEM);
        cudaFuncSetAttribute(attn_mma, cudaFuncAttributeMaxDynamicSharedMemorySize, ATTN_SMEM);
        attr_set = true;
    }

    // projections (tf32 tensor cores)
    gemm_tf32<<<dim3(QCOLS_/128, BT_/128), 256, GEMM_SMEM>>>(x, wq, q, BT_, QCOLS_, D_);
    gemm_tf32<<<dim3(KCOLS_/128, BT_/128), 256, GEMM_SMEM>>>(x, wk, k, BT_, KCOLS_, D_);
    gemm_tf32<<<dim3(KCOLS_/128, BT_/128), 256, GEMM_SMEM>>>(x, wv, v, BT_, KCOLS_, D_);

    // QK-norm (fold attention scale into q)
    rmsnorm_k<<<(BT_*H_)/8, 256>>>(q, qg, BT_*H_, SCALE_);
    rmsnorm_k<<<(BT_*KVH_)/8, 256>>>(k, kg, BT_*KVH_, 1.0f);

    // attention (tf32 tensor cores, split-key warps + epilogue merge)
    attn_mma<<<dim3(T_/64, B_*H_), 128, ATTN_SMEM>>>(q, k, v, o);

    // output projection
    gemm_tf32<<<dim3(D_/128, BT_/128), 256, GEMM_SMEM>>>(o, wo, out, BT_, D_, D_);
}